// round 10
// baseline (speedup 1.0000x reference)
#include <cuda_runtime.h>
#include <cstdint>

// DeepProbLogAdditionReasoner: per-row conv of two length-10 pdfs -> 19 bins, normalized.
// Round-10: warp-autonomous pipelines. Each warp owns a 32-row slice per tile,
// runs its own double-buffered cp.async input pipeline (per-thread group state),
// stages output in its own smem slice, and stores coalesced float4.
// ZERO __syncthreads in the main loop -- only __syncwarp. Warps never wait on
// each other's memory stalls.

#define TPB 128
#define WARPS 4
#define WROWS 32                   // rows per warp per tile
#define WSLICE_F (WROWS * 20)      // 640 floats: p1 slice (320) | p2 slice (320)
#define WV4_IN  (WROWS * 10 / 4)   // 80 float4 per input array per warp-slice
#define WOUT_F  (WROWS * 19)       // 608 floats output per warp
#define WV4_OUT (WOUT_F / 4)       // 152 float4
#define MAXGRID (152 * 7)

__device__ __forceinline__ uint32_t smem_u32(const void* p) {
    uint32_t a;
    asm("{ .reg .u64 t; cvta.to.shared.u64 t, %1; cvt.u32.u64 %0, t; }"
        : "=r"(a) : "l"(p));
    return a;
}

__device__ __forceinline__ void cp_async16(uint32_t smem_dst, const void* gmem_src) {
    asm volatile("cp.async.cg.shared.global [%0], [%1], 16;"
                 :: "r"(smem_dst), "l"(gmem_src) : "memory");
}

__global__ __launch_bounds__(TPB) void dpl_add_kernel(
    const float* __restrict__ p1,
    const float* __restrict__ p2,
    float* __restrict__ out,
    int B, int nTiles)
{
    __shared__ float sin[2][TPB * 20];   // per warp: slice at wid*640
    __shared__ float sout[TPB * 19];     // per warp: slice at wid*608

    const int tid  = threadIdx.x;
    const int wid  = tid >> 5;
    const int lane = tid & 31;
    const int stride = gridDim.x;

    float* const soutW = sout + wid * WOUT_F;

    // per-warp prefetch of tile t's 32-row slice into sin[buf]
    auto prefetch = [&](int t, int buf) {
        const long long rbase = (long long)t * TPB + wid * WROWS;
        const float4* g14 = (const float4*)(p1 + rbase * 10);
        const float4* g24 = (const float4*)(p2 + rbase * 10);
        const uint32_t sb = smem_u32(&sin[buf][wid * WSLICE_F]);
        #pragma unroll
        for (int i = lane; i < WV4_IN; i += 32) {
            cp_async16(sb + i * 16,               g14 + i);
            cp_async16(sb + (WV4_IN + i) * 16,    g24 + i);
        }
    };

    int tile = blockIdx.x;

    // ---- prologue ----
    if (tile < nTiles && (long long)tile * TPB + TPB <= (long long)B)
        prefetch(tile, 0);
    asm volatile("cp.async.commit_group;" ::: "memory");

    for (int k = 0; tile < nTiles; k++, tile += stride) {
        const int cur = k & 1;
        const long long base = (long long)tile * TPB;
        const long long wbase = base + wid * WROWS;   // this warp's first row
        const bool full = (base + TPB <= (long long)B);

        // ---- prefetch next tile's slice into the other buffer ----
        const int nextTile = tile + stride;
        if (nextTile < nTiles && (long long)nextTile * TPB + TPB <= (long long)B)
            prefetch(nextTile, cur ^ 1);
        asm volatile("cp.async.commit_group;" ::: "memory");

        // ---- this warp's current slice ready; next stays in flight ----
        asm volatile("cp.async.wait_group 1;" ::: "memory");

        float* const sl = &sin[cur][wid * WSLICE_F];
        const long long row = wbase + lane;
        const bool have = (row < B);

        if (!full && have) {   // rare tail: scalar synchronous load of own row
            const float* g1 = p1 + row * 10;
            const float* g2 = p2 + row * 10;
            #pragma unroll
            for (int i = 0; i < 10; i++) {
                sl[lane * 10 + i]               = g1[i];
                sl[WROWS * 10 + lane * 10 + i]  = g2[i];
            }
        }
        __syncwarp();   // cross-lane visibility of staged slice

        // ---- compute: per-row convolution + normalize ----
        float r[19];
        if (have) {
            float a[10], b[10];
            #pragma unroll
            for (int i = 0; i < 10; i++) {
                a[i] = sl[lane * 10 + i];
                b[i] = sl[WROWS * 10 + lane * 10 + i];
            }
            #pragma unroll
            for (int q = 0; q < 19; q++) r[q] = 0.0f;
            #pragma unroll
            for (int i = 0; i < 10; i++) {
                #pragma unroll
                for (int j = 0; j < 10; j++)
                    r[i + j] = fmaf(a[i], b[j], r[i + j]);
            }
            float s = 0.0f;
            #pragma unroll
            for (int q = 0; q < 19; q++) s += r[q];
            const float inv = 1.0f / (s + 1e-9f);
            #pragma unroll
            for (int q = 0; q < 19; q++) r[q] *= inv;
        }
        __syncwarp();   // prior iter's sout reads are done on all lanes

        // ---- stage to warp sout slice (stride 19: conflict-free) ----
        if (have) {
            #pragma unroll
            for (int q = 0; q < 19; q++) soutW[lane * 19 + q] = r[q];
        }
        __syncwarp();

        // ---- coalesced store of this warp's 608 floats ----
        if (full) {
            float4* go4 = (float4*)(out + wbase * 19);
            const float4* so4 = (const float4*)soutW;
            #pragma unroll
            for (int i = lane; i < WV4_OUT; i += 32)
                go4[i] = so4[i];
        } else {
            const int wrows = (B - wbase > 0)
                            ? ((B - wbase < WROWS) ? (int)(B - wbase) : WROWS) : 0;
            float* go = out + wbase * 19;
            const int n = wrows * 19;
            for (int i = lane; i < n; i += 32) go[i] = soutW[i];
        }
    }
}

extern "C" void kernel_launch(void* const* d_in, const int* in_sizes, int n_in,
                              void* d_out, int out_size) {
    const float* p1 = (const float*)d_in[0];
    const float* p2 = (const float*)d_in[1];
    float* out = (float*)d_out;
    const int B = in_sizes[0] / 10;
    const int nTiles = (B + TPB - 1) / TPB;
    int grid = nTiles;
    if (grid > MAXGRID) {
        const int tilesPerCta = (nTiles + MAXGRID - 1) / MAXGRID;
        grid = (nTiles + tilesPerCta - 1) / tilesPerCta;
    }
    dpl_add_kernel<<<grid, TPB>>>(p1, p2, out, B, nTiles);
}

// round 11
// speedup vs baseline: 1.0146x; 1.0146x over previous
#include <cuda_runtime.h>
#include <cstdint>

// DeepProbLogAdditionReasoner: per-row conv of two length-10 pdfs -> 19 bins, normalized.
// Round-11: R4 structure (best steady-state wall) scaled to TPB=512 for longer
// DRAM bursts: 2x20KB contiguous cp.async reads and one 38.9KB bulk store per CTA,
// reducing read<->write turnaround frequency at the memory controller.
//   - cp.async.cg 16B input staging (register-free)
//   - per-row 10x10 FMA conv + normalize
//   - output restaged into the same smem buffer -> single TMA bulk store
//   - __launch_bounds__(512,4): 64 warps/SM (100% theoretical occ), regs<=32

#define TPB 512
#define NV4_IN  (TPB * 10 / 4)    // 1280 float4 per input array per block
#define OUT_BYTES (TPB * 19 * 4)  // 38912 bytes output tile per block

__device__ __forceinline__ uint32_t smem_u32(const void* p) {
    uint32_t a;
    asm("{ .reg .u64 t; cvta.to.shared.u64 t, %1; cvt.u32.u64 %0, t; }"
        : "=r"(a) : "l"(p));
    return a;
}

__device__ __forceinline__ void cp_async16(uint32_t smem_dst, const void* gmem_src) {
    asm volatile("cp.async.cg.shared.global [%0], [%1], 16;"
                 :: "r"(smem_dst), "l"(gmem_src) : "memory");
}

__global__ __launch_bounds__(TPB, 4) void dpl_add_kernel(
    const float* __restrict__ p1,
    const float* __restrict__ p2,
    float* __restrict__ out,
    int B)
{
    // phase 1: [0 .. TPB*10) = p1 rows, [TPB*10 .. TPB*20) = p2 rows (linear pitch 10)
    // phase 3: [0 .. TPB*19) = output rows (stride 19) -- same buffer
    __shared__ float sm[TPB * 20];
    float4* sm4 = (float4*)sm;

    const int tid = threadIdx.x;
    const long long base = (long long)blockIdx.x * TPB;
    const int rows = (B - base < TPB) ? (int)(B - base) : TPB;
    const bool full = (rows == TPB);

    // ---- Phase 1: async vectorized global -> smem (no register round-trip) ----
    if (full) {
        const float4* g14 = (const float4*)(p1 + base * 10);
        const float4* g24 = (const float4*)(p2 + base * 10);
        const uint32_t s_base = smem_u32(sm4);
        #pragma unroll
        for (int i = tid; i < NV4_IN; i += TPB) {
            cp_async16(s_base + i * 16,            g14 + i);
            cp_async16(s_base + (NV4_IN + i) * 16, g24 + i);
        }
        asm volatile("cp.async.commit_group;" ::: "memory");
        asm volatile("cp.async.wait_group 0;" ::: "memory");
    } else {
        const float* g1 = p1 + base * 10;
        const float* g2 = p2 + base * 10;
        const int nElems = rows * 10;
        for (int i = tid; i < nElems; i += TPB) {
            sm[i]            = g1[i];
            sm[TPB * 10 + i] = g2[i];
        }
    }
    __syncthreads();

    // ---- Phase 2: per-row convolution + normalize in registers ----
    float r[19];
    if (tid < rows) {
        float a[10], b[10];
        #pragma unroll
        for (int i = 0; i < 10; i++) {
            a[i] = sm[tid * 10 + i];
            b[i] = sm[TPB * 10 + tid * 10 + i];
        }
        #pragma unroll
        for (int k = 0; k < 19; k++) r[k] = 0.0f;
        #pragma unroll
        for (int i = 0; i < 10; i++) {
            #pragma unroll
            for (int j = 0; j < 10; j++) {
                r[i + j] = fmaf(a[i], b[j], r[i + j]);
            }
        }
        float s = 0.0f;
        #pragma unroll
        for (int k = 0; k < 19; k++) s += r[k];
        float inv = 1.0f / (s + 1e-9f);
        #pragma unroll
        for (int k = 0; k < 19; k++) r[k] *= inv;
    }

    __syncthreads();   // inputs consumed; smem reusable for output staging

    // ---- Phase 3: smem stage (stride 19) -> one large TMA bulk store ----
    if (tid < rows) {
        #pragma unroll
        for (int k = 0; k < 19; k++) sm[tid * 19 + k] = r[k];
    }
    __syncthreads();

    if (full) {
        if (tid == 0) {
            asm volatile("fence.proxy.async.shared::cta;" ::: "memory");
            float* go = out + base * 19;
            asm volatile(
                "cp.async.bulk.global.shared::cta.bulk_group [%0], [%1], %2;"
                :: "l"(go), "r"(smem_u32(sm)), "r"((uint32_t)OUT_BYTES)
                : "memory");
            asm volatile("cp.async.bulk.commit_group;" ::: "memory");
            asm volatile("cp.async.bulk.wait_group 0;" ::: "memory");
        }
        // other threads retire; CTA smem stays alive until tid 0 finishes
    } else {
        float* go = out + base * 19;
        const int nOut = rows * 19;
        for (int i = tid; i < nOut; i += TPB) go[i] = sm[i];
    }
}

extern "C" void kernel_launch(void* const* d_in, const int* in_sizes, int n_in,
                              void* d_out, int out_size) {
    const float* p1 = (const float*)d_in[0];
    const float* p2 = (const float*)d_in[1];
    float* out = (float*)d_out;
    const int B = in_sizes[0] / 10;
    const int grid = (B + TPB - 1) / TPB;
    dpl_add_kernel<<<grid, TPB>>>(p1, p2, out, B);
}